// round 5
// baseline (speedup 1.0000x reference)
#include <cuda_runtime.h>
#include <cstdint>
#include <cstddef>

#define NN 16384
#define DD 512

// ---------------- scratch (device globals; sanctioned, no runtime alloc) -----
__device__ float g_simT[(size_t)NN * NN];   // simT[i][j] = <R_i, L_j> = sim[j][i]
__device__ float g_LR[NN];                  // mean top-10 of col j of simT (= row j of sim)
__device__ float g_RL[NN];                  // mean top-10 of simT rows
__device__ float g_P [NN];                  // LR + RL

// ---------------- SIMT fp32 GEMM: C[i][j] = sum_k A[i][k]*B[j][k] -------------
// BM=BN=128, BK=8, 256 threads, 8x8 per thread. No tensor cores, no asm.
#define BM 128
#define BN 128
#define BK 8

__global__ __launch_bounds__(256)
void gemm_fp32(const float* __restrict__ A, const float* __restrict__ B) {
    __shared__ float As[BK][BM];
    __shared__ float Bs[BK][BN];

    const int bm = blockIdx.y * BM;
    const int bn = blockIdx.x * BN;
    const int tid = threadIdx.x;
    const int tx = tid & 15;          // 0..15 -> n direction
    const int ty = tid >> 4;          // 0..15 -> m direction

    const int lrow = tid >> 1;        // 0..127
    const int lc4  = (tid & 1) * 4;   // 0 or 4

    float acc[8][8];
#pragma unroll
    for (int a = 0; a < 8; a++)
#pragma unroll
        for (int b = 0; b < 8; b++) acc[a][b] = 0.0f;

    for (int k0 = 0; k0 < DD; k0 += BK) {
        float4 va = *(const float4*)&A[(size_t)(bm + lrow) * DD + k0 + lc4];
        float4 vb = *(const float4*)&B[(size_t)(bn + lrow) * DD + k0 + lc4];
        __syncthreads();
        As[lc4 + 0][lrow] = va.x;
        As[lc4 + 1][lrow] = va.y;
        As[lc4 + 2][lrow] = va.z;
        As[lc4 + 3][lrow] = va.w;
        Bs[lc4 + 0][lrow] = vb.x;
        Bs[lc4 + 1][lrow] = vb.y;
        Bs[lc4 + 2][lrow] = vb.z;
        Bs[lc4 + 3][lrow] = vb.w;
        __syncthreads();

#pragma unroll
        for (int kk = 0; kk < BK; kk++) {
            float ra[8], rb[8];
#pragma unroll
            for (int q = 0; q < 8; q++) ra[q] = As[kk][ty * 8 + q];
#pragma unroll
            for (int q = 0; q < 8; q++) rb[q] = Bs[kk][tx * 8 + q];
#pragma unroll
            for (int a = 0; a < 8; a++)
#pragma unroll
                for (int b = 0; b < 8; b++)
                    acc[a][b] = fmaf(ra[a], rb[b], acc[a][b]);
        }
    }

#pragma unroll
    for (int a = 0; a < 8; a++) {
        int m = bm + ty * 8 + a;
        int n = bn + tx * 8;
        *(float4*)&g_simT[(size_t)m * NN + n] =
            make_float4(acc[a][0], acc[a][1], acc[a][2], acc[a][3]);
        *(float4*)&g_simT[(size_t)m * NN + n + 4] =
            make_float4(acc[a][4], acc[a][5], acc[a][6], acc[a][7]);
    }
}

// ---------------- top-10 insertion (t ascending; t[0] = current min) ----------
__device__ __forceinline__ void insert10(float* t, float v) {
    if (v > t[0]) {
        t[0] = v;
#pragma unroll
        for (int i = 0; i < 9; i++) {
            if (t[i] > t[i + 1]) { float tmp = t[i]; t[i] = t[i + 1]; t[i + 1] = tmp; }
        }
    }
}

#define SENT (-1e30f)

// ---------------- RL: per-row top-10 mean of simT ----------------------------
__global__ __launch_bounds__(256)
void row_topk_mean() {
    __shared__ float s[256 * 10];
    const int row = blockIdx.x;
    const int tid = threadIdx.x;
    const float4* p = (const float4*)(g_simT + (size_t)row * NN);

    float t[10];
#pragma unroll
    for (int i = 0; i < 10; i++) t[i] = SENT;

    for (int j = tid; j < NN / 4; j += 256) {
        float4 v = p[j];
        insert10(t, v.x); insert10(t, v.y); insert10(t, v.z); insert10(t, v.w);
    }
#pragma unroll
    for (int i = 0; i < 10; i++) s[tid * 10 + i] = t[i];
    __syncthreads();

    if (tid < 32) {
#pragma unroll
        for (int i = 0; i < 10; i++) t[i] = s[tid * 10 + i];
        for (int src = tid + 32; src < 256; src += 32)
#pragma unroll
            for (int i = 0; i < 10; i++) insert10(t, s[src * 10 + i]);
#pragma unroll
        for (int i = 0; i < 10; i++) s[tid * 10 + i] = t[i];
    }
    __syncthreads();

    if (tid == 0) {
#pragma unroll
        for (int i = 0; i < 10; i++) t[i] = s[i];
        for (int src = 1; src < 32; src++)
#pragma unroll
            for (int i = 0; i < 10; i++) insert10(t, s[src * 10 + i]);
        float sum = 0.0f;
#pragma unroll
        for (int i = 0; i < 10; i++) sum += t[i];
        g_RL[row] = sum * 0.1f;
    }
}

// ---------------- LR: per-column top-10 mean of simT -------------------------
__global__ __launch_bounds__(256)
void col_topk_mean() {
    __shared__ float s[256 * 10];
    const int tid = threadIdx.x;
    const int col = blockIdx.x * 64 + (tid & 63);
    const int q   = tid >> 6;   // 0..3

    float t[10];
#pragma unroll
    for (int i = 0; i < 10; i++) t[i] = SENT;

    const float* base = g_simT + (size_t)q * 4096 * NN + col;
    for (int r = 0; r < 4096; r++) {
        insert10(t, base[(size_t)r * NN]);
    }
#pragma unroll
    for (int i = 0; i < 10; i++) s[tid * 10 + i] = t[i];
    __syncthreads();

    if (q == 0) {
#pragma unroll
        for (int p = 1; p < 4; p++)
#pragma unroll
            for (int i = 0; i < 10; i++) insert10(t, s[(tid + p * 64) * 10 + i]);
        float sum = 0.0f;
#pragma unroll
        for (int i = 0; i < 10; i++) sum += t[i];
        g_LR[col] = sum * 0.1f;
    }
}

// ---------------- P = LR + RL ------------------------------------------------
__global__ void compute_p() {
    int i = blockIdx.x * 256 + threadIdx.x;
    g_P[i] = g_LR[i] + g_RL[i];
}

// ---------------- rank + top1 over csls rows ---------------------------------
// csls[i][j] = 2*simT[i][j] - P[j]
// rank[i] = #{j: csls>d} + #{j<i: csls==d},  d = csls[i][i]  (stable argsort)
// NOTE: ranks are written as FLOAT — the harness output buffer is float32 for
// the whole tuple; int32 bit patterns read as float are denormals (~0), which
// produced the exact rel_err=1.0 failures of rounds 1-4.
__global__ __launch_bounds__(256)
void rank_top1(float* __restrict__ ranks, float* __restrict__ top1) {
    __shared__ int   s_gt[256];
    __shared__ int   s_eq[256];
    __shared__ float s_mx[256];

    const int i   = blockIdx.x;
    const int tid = threadIdx.x;
    const float* prow = g_simT + (size_t)i * NN;
    const float d = 2.0f * prow[i] - g_P[i];

    int cnt_gt = 0, cnt_eq = 0;
    float mx = SENT;

    const float4* pv = (const float4*)prow;
    const float4* qv = (const float4*)g_P;
    for (int j4 = tid; j4 < NN / 4; j4 += 256) {
        float4 v = pv[j4];
        float4 q = qv[j4];
        int j = j4 * 4;
        float c0 = 2.0f * v.x - q.x;
        float c1 = 2.0f * v.y - q.y;
        float c2 = 2.0f * v.z - q.z;
        float c3 = 2.0f * v.w - q.w;
        cnt_gt += (c0 > d) + (c1 > d) + (c2 > d) + (c3 > d);
        if (c0 == d && (j + 0) < i) cnt_eq++;
        if (c1 == d && (j + 1) < i) cnt_eq++;
        if (c2 == d && (j + 2) < i) cnt_eq++;
        if (c3 == d && (j + 3) < i) cnt_eq++;
        mx = fmaxf(mx, fmaxf(fmaxf(c0, c1), fmaxf(c2, c3)));
    }

    s_gt[tid] = cnt_gt; s_eq[tid] = cnt_eq; s_mx[tid] = mx;
    __syncthreads();
    for (int str = 128; str > 0; str >>= 1) {
        if (tid < str) {
            s_gt[tid] += s_gt[tid + str];
            s_eq[tid] += s_eq[tid + str];
            s_mx[tid] = fmaxf(s_mx[tid], s_mx[tid + str]);
        }
        __syncthreads();
    }
    if (tid == 0) {
        ranks[i] = (float)(s_gt[0] + s_eq[0]);   // ranks as float32
        top1[i]  = s_mx[0];
    }
}

// ---------------- launch (kernel launches only; idempotent) -------------------
extern "C" void kernel_launch(void* const* d_in, const int* in_sizes, int n_in,
                              void* d_out, int out_size) {
    const float* L = (const float*)d_in[0];
    const float* R = (const float*)d_in[1];

    // simT = R . L^T   (simT[i][j] = <R_i, L_j>)
    dim3 grid(NN / BN, NN / BM);
    gemm_fp32<<<grid, 256>>>(R, L);

    row_topk_mean<<<NN, 256>>>();        // RL over simT rows
    col_topk_mean<<<NN / 64, 256>>>();   // LR over simT cols
    compute_p<<<NN / 256, 256>>>();

    float* ranks = (float*)d_out;
    float* top1  = (float*)d_out + NN;
    rank_top1<<<NN, 256>>>(ranks, top1);
}

// round 6
// speedup vs baseline: 1.2981x; 1.2981x over previous
#include <cuda_runtime.h>
#include <cstdint>
#include <cstddef>

#define NN 16384
#define DD 512

// ---------------- scratch (device globals; sanctioned, no runtime alloc) -----
__device__ float g_simT[(size_t)NN * NN];   // simT[i][j] = <R_i, L_j> = sim[j][i]
__device__ float g_LR[NN];                  // mean top-10 of col j of simT (= row j of sim)
__device__ float g_RL[NN];                  // mean top-10 of simT rows
__device__ float g_P [NN];                  // LR + RL

// ---------------- helpers ----------------------------------------------------
__device__ __forceinline__ uint32_t f2tf(float x) {
    uint32_t r;
    asm("cvt.rna.tf32.f32 %0, %1;" : "=r"(r) : "f"(x));
    return r;
}

__device__ __forceinline__ void mma_tf32(float* c, const uint32_t* a, uint32_t b0, uint32_t b1) {
    asm volatile(
        "mma.sync.aligned.m16n8k8.row.col.f32.tf32.tf32.f32 "
        "{%0,%1,%2,%3}, {%4,%5,%6,%7}, {%8,%9}, {%0,%1,%2,%3};"
        : "+f"(c[0]), "+f"(c[1]), "+f"(c[2]), "+f"(c[3])
        : "r"(a[0]), "r"(a[1]), "r"(a[2]), "r"(a[3]), "r"(b0), "r"(b1));
}

// ---------------- GEMM (3xTF32): C[i][j] = sum_k A[i][k]*B[j][k] --------------
// hi/lo split: C = Ahi*Bhi + Ahi*Blo + Alo*Bhi  (~fp32 accuracy)
// Static shared memory (40 KB), single-buffered, BK=16.
#define BM 128
#define BN 128
#define BK 16
#define SST 20   // padded smem row stride (uint32)

__global__ __launch_bounds__(256)
void gemm_3xtf32(const float* __restrict__ A, const float* __restrict__ B) {
    __shared__ uint32_t Ahi[BM * SST];
    __shared__ uint32_t Alo[BM * SST];
    __shared__ uint32_t Bhi[BN * SST];
    __shared__ uint32_t Blo[BN * SST];

    const int bm = blockIdx.y * BM;
    const int bn = blockIdx.x * BN;
    const int tid  = threadIdx.x;
    const int warp = tid >> 5;
    const int lane = tid & 31;
    const int wm = (warp & 3) * 32;   // 4x2 warp grid; warp tile 32(m) x 64(n)
    const int wn = (warp >> 2) * 64;

    // per chunk: 128x16 floats = 512 float4 per matrix; 256 threads x 2
    const int l_row  = tid >> 2;
    const int l_c4   = (tid & 3) << 2;
    const int l_row2 = (tid + 256) >> 2;
    const int l_c42  = ((tid + 256) & 3) << 2;

    float4 ra0, ra1, rb0, rb1;

    auto load_regs = [&](int k0) {
        ra0 = *(const float4*)&A[(size_t)(bm + l_row ) * DD + k0 + l_c4 ];
        ra1 = *(const float4*)&A[(size_t)(bm + l_row2) * DD + k0 + l_c42];
        rb0 = *(const float4*)&B[(size_t)(bn + l_row ) * DD + k0 + l_c4 ];
        rb1 = *(const float4*)&B[(size_t)(bn + l_row2) * DD + k0 + l_c42];
    };

    auto cvt_store = [&](uint32_t* hi, uint32_t* lo, int row, int c4, float4 v) {
        uint32_t h0 = f2tf(v.x), h1 = f2tf(v.y), h2 = f2tf(v.z), h3 = f2tf(v.w);
        uint32_t l0 = f2tf(v.x - __uint_as_float(h0));
        uint32_t l1 = f2tf(v.y - __uint_as_float(h1));
        uint32_t l2 = f2tf(v.z - __uint_as_float(h2));
        uint32_t l3 = f2tf(v.w - __uint_as_float(h3));
        *(uint4*)&hi[row * SST + c4] = make_uint4(h0, h1, h2, h3);
        *(uint4*)&lo[row * SST + c4] = make_uint4(l0, l1, l2, l3);
    };

    float acc[2][8][4];
#pragma unroll
    for (int im = 0; im < 2; im++)
#pragma unroll
        for (int in = 0; in < 8; in++)
#pragma unroll
            for (int q = 0; q < 4; q++) acc[im][in][q] = 0.0f;

    load_regs(0);

    const int NCHUNK = DD / BK;   // 32
    for (int c = 0; c < NCHUNK; c++) {
        __syncthreads();   // previous chunk's compute done
        cvt_store(Ahi, Alo, l_row,  l_c4,  ra0);
        cvt_store(Ahi, Alo, l_row2, l_c42, ra1);
        cvt_store(Bhi, Blo, l_row,  l_c4,  rb0);
        cvt_store(Bhi, Blo, l_row2, l_c42, rb1);
        __syncthreads();

        if (c + 1 < NCHUNK) load_regs((c + 1) * BK);   // overlap with MMA below

#pragma unroll
        for (int kk = 0; kk < BK; kk += 8) {
            const int mrow = lane >> 2;
            const int kc = kk + (lane & 3);
            uint32_t afh[2][4], afl[2][4];
#pragma unroll
            for (int im = 0; im < 2; im++) {
                int m = wm + im * 16 + mrow;
                afh[im][0] = Ahi[(m    ) * SST + kc    ];
                afh[im][1] = Ahi[(m + 8) * SST + kc    ];
                afh[im][2] = Ahi[(m    ) * SST + kc + 4];
                afh[im][3] = Ahi[(m + 8) * SST + kc + 4];
                afl[im][0] = Alo[(m    ) * SST + kc    ];
                afl[im][1] = Alo[(m + 8) * SST + kc    ];
                afl[im][2] = Alo[(m    ) * SST + kc + 4];
                afl[im][3] = Alo[(m + 8) * SST + kc + 4];
            }
#pragma unroll
            for (int in = 0; in < 8; in++) {
                int n = wn + in * 8 + mrow;
                uint32_t bh0 = Bhi[n * SST + kc    ];
                uint32_t bh1 = Bhi[n * SST + kc + 4];
                uint32_t bl0 = Blo[n * SST + kc    ];
                uint32_t bl1 = Blo[n * SST + kc + 4];
#pragma unroll
                for (int im = 0; im < 2; im++) {
                    mma_tf32(acc[im][in], afh[im], bh0, bh1);  // hi*hi
                    mma_tf32(acc[im][in], afh[im], bl0, bl1);  // hi*lo
                    mma_tf32(acc[im][in], afl[im], bh0, bh1);  // lo*hi
                }
            }
        }
    }

    // epilogue
#pragma unroll
    for (int im = 0; im < 2; im++) {
#pragma unroll
        for (int in = 0; in < 8; in++) {
            int m = bm + wm + im * 16 + (lane >> 2);
            int n = bn + wn + in * 8 + 2 * (lane & 3);
            *(float2*)&g_simT[(size_t)m * NN + n]       = make_float2(acc[im][in][0], acc[im][in][1]);
            *(float2*)&g_simT[(size_t)(m + 8) * NN + n] = make_float2(acc[im][in][2], acc[im][in][3]);
        }
    }
}

// ---------------- top-10 insertion (t ascending; t[0] = current min) ----------
__device__ __forceinline__ void insert10(float* t, float v) {
    if (v > t[0]) {
        t[0] = v;
#pragma unroll
        for (int i = 0; i < 9; i++) {
            if (t[i] > t[i + 1]) { float tmp = t[i]; t[i] = t[i + 1]; t[i + 1] = tmp; }
        }
    }
}

#define SENT (-1e30f)

// ---------------- RL: per-row top-10 mean of simT ----------------------------
__global__ __launch_bounds__(256)
void row_topk_mean() {
    __shared__ float s[256 * 10];
    const int row = blockIdx.x;
    const int tid = threadIdx.x;
    const float4* p = (const float4*)(g_simT + (size_t)row * NN);

    float t[10];
#pragma unroll
    for (int i = 0; i < 10; i++) t[i] = SENT;

    for (int j = tid; j < NN / 4; j += 256) {
        float4 v = p[j];
        insert10(t, v.x); insert10(t, v.y); insert10(t, v.z); insert10(t, v.w);
    }
#pragma unroll
    for (int i = 0; i < 10; i++) s[tid * 10 + i] = t[i];
    __syncthreads();

    if (tid < 32) {
#pragma unroll
        for (int i = 0; i < 10; i++) t[i] = s[tid * 10 + i];
        for (int src = tid + 32; src < 256; src += 32)
#pragma unroll
            for (int i = 0; i < 10; i++) insert10(t, s[src * 10 + i]);
#pragma unroll
        for (int i = 0; i < 10; i++) s[tid * 10 + i] = t[i];
    }
    __syncthreads();

    if (tid == 0) {
#pragma unroll
        for (int i = 0; i < 10; i++) t[i] = s[i];
        for (int src = 1; src < 32; src++)
#pragma unroll
            for (int i = 0; i < 10; i++) insert10(t, s[src * 10 + i]);
        float sum = 0.0f;
#pragma unroll
        for (int i = 0; i < 10; i++) sum += t[i];
        g_RL[row] = sum * 0.1f;
    }
}

// ---------------- LR: per-column top-10 mean of simT -------------------------
__global__ __launch_bounds__(256)
void col_topk_mean() {
    __shared__ float s[256 * 10];
    const int tid = threadIdx.x;
    const int col = blockIdx.x * 64 + (tid & 63);
    const int q   = tid >> 6;   // 0..3

    float t[10];
#pragma unroll
    for (int i = 0; i < 10; i++) t[i] = SENT;

    const float* base = g_simT + (size_t)q * 4096 * NN + col;
    for (int r = 0; r < 4096; r++) {
        insert10(t, base[(size_t)r * NN]);
    }
#pragma unroll
    for (int i = 0; i < 10; i++) s[tid * 10 + i] = t[i];
    __syncthreads();

    if (q == 0) {
#pragma unroll
        for (int p = 1; p < 4; p++)
#pragma unroll
            for (int i = 0; i < 10; i++) insert10(t, s[(tid + p * 64) * 10 + i]);
        float sum = 0.0f;
#pragma unroll
        for (int i = 0; i < 10; i++) sum += t[i];
        g_LR[col] = sum * 0.1f;
    }
}

// ---------------- P = LR + RL ------------------------------------------------
__global__ void compute_p() {
    int i = blockIdx.x * 256 + threadIdx.x;
    g_P[i] = g_LR[i] + g_RL[i];
}

// ---------------- rank + top1 over csls rows ---------------------------------
// csls[i][j] = 2*simT[i][j] - P[j]
// rank[i] = #{j: csls>d} + #{j<i: csls==d},  d = csls[i][i]  (stable argsort)
// Ranks written as FLOAT (harness output buffer is float32 for the whole tuple).
__global__ __launch_bounds__(256)
void rank_top1(float* __restrict__ ranks, float* __restrict__ top1) {
    __shared__ int   s_gt[256];
    __shared__ int   s_eq[256];
    __shared__ float s_mx[256];

    const int i   = blockIdx.x;
    const int tid = threadIdx.x;
    const float* prow = g_simT + (size_t)i * NN;
    const float d = 2.0f * prow[i] - g_P[i];

    int cnt_gt = 0, cnt_eq = 0;
    float mx = SENT;

    const float4* pv = (const float4*)prow;
    const float4* qv = (const float4*)g_P;
    for (int j4 = tid; j4 < NN / 4; j4 += 256) {
        float4 v = pv[j4];
        float4 q = qv[j4];
        int j = j4 * 4;
        float c0 = 2.0f * v.x - q.x;
        float c1 = 2.0f * v.y - q.y;
        float c2 = 2.0f * v.z - q.z;
        float c3 = 2.0f * v.w - q.w;
        cnt_gt += (c0 > d) + (c1 > d) + (c2 > d) + (c3 > d);
        if (c0 == d && (j + 0) < i) cnt_eq++;
        if (c1 == d && (j + 1) < i) cnt_eq++;
        if (c2 == d && (j + 2) < i) cnt_eq++;
        if (c3 == d && (j + 3) < i) cnt_eq++;
        mx = fmaxf(mx, fmaxf(fmaxf(c0, c1), fmaxf(c2, c3)));
    }

    s_gt[tid] = cnt_gt; s_eq[tid] = cnt_eq; s_mx[tid] = mx;
    __syncthreads();
    for (int str = 128; str > 0; str >>= 1) {
        if (tid < str) {
            s_gt[tid] += s_gt[tid + str];
            s_eq[tid] += s_eq[tid + str];
            s_mx[tid] = fmaxf(s_mx[tid], s_mx[tid + str]);
        }
        __syncthreads();
    }
    if (tid == 0) {
        ranks[i] = (float)(s_gt[0] + s_eq[0]);   // ranks as float32
        top1[i]  = s_mx[0];
    }
}

// ---------------- launch (kernel launches only; idempotent) -------------------
extern "C" void kernel_launch(void* const* d_in, const int* in_sizes, int n_in,
                              void* d_out, int out_size) {
    const float* L = (const float*)d_in[0];
    const float* R = (const float*)d_in[1];

    // simT = R . L^T   (simT[i][j] = <R_i, L_j>)
    dim3 grid(NN / BN, NN / BM);
    gemm_3xtf32<<<grid, 256>>>(R, L);

    row_topk_mean<<<NN, 256>>>();        // RL over simT rows
    col_topk_mean<<<NN / 64, 256>>>();   // LR over simT cols
    compute_p<<<NN / 256, 256>>>();

    float* ranks = (float*)d_out;
    float* top1  = (float*)d_out + NN;
    rank_top1<<<NN, 256>>>(ranks, top1);
}

// round 7
// speedup vs baseline: 1.7062x; 1.3144x over previous
#include <cuda_runtime.h>
#include <cuda_fp16.h>
#include <cstdint>
#include <cstddef>

#define NN 16384
#define DD 512
#define WPR 256   // half2 words per row (DD/2)

// ---------------- scratch (device globals; sanctioned) ------------------------
__device__ float    g_simT[(size_t)NN * NN]; // simT[i][j] = <R_i, L_j>
__device__ uint32_t g_Lhi[(size_t)NN * WPR];
__device__ uint32_t g_Llo[(size_t)NN * WPR];
__device__ uint32_t g_Rhi[(size_t)NN * WPR];
__device__ uint32_t g_Rlo[(size_t)NN * WPR];
__device__ float    g_LR[NN];
__device__ float    g_RL[NN];
__device__ float    g_P [NN];

// ---------------- precompute: fp16 hi/lo split, packed half2 ------------------
__global__ __launch_bounds__(256)
void cvt_hl(const float* __restrict__ L, const float* __restrict__ R) {
    const size_t w = (size_t)blockIdx.x * 256 + threadIdx.x;   // word index
    const float2* src = (blockIdx.y == 0) ? (const float2*)L : (const float2*)R;
    uint32_t* dhi = (blockIdx.y == 0) ? g_Lhi : g_Rhi;
    uint32_t* dlo = (blockIdx.y == 0) ? g_Llo : g_Rlo;

    float2 v = src[w];
    __half hx = __float2half_rn(v.x);
    __half hy = __float2half_rn(v.y);
    float lx = v.x - __half2float(hx);
    float ly = v.y - __half2float(hy);
    __half2 hhi = __halves2half2(hx, hy);
    __half2 hlo = __floats2half2_rn(lx, ly);
    dhi[w] = *(uint32_t*)&hhi;
    dlo[w] = *(uint32_t*)&hlo;
}

// ---------------- fp16 3-term MMA -------------------------------------------
__device__ __forceinline__ void mma_f16(float* c, const uint32_t* a, uint32_t b0, uint32_t b1) {
    asm volatile(
        "mma.sync.aligned.m16n8k16.row.col.f32.f16.f16.f32 "
        "{%0,%1,%2,%3}, {%4,%5,%6,%7}, {%8,%9}, {%0,%1,%2,%3};"
        : "+f"(c[0]), "+f"(c[1]), "+f"(c[2]), "+f"(c[3])
        : "r"(a[0]), "r"(a[1]), "r"(a[2]), "r"(a[3]), "r"(b0), "r"(b1));
}

// ---------------- GEMM: simT = R . L^T  (3-term fp16 split) -------------------
// BM=BN=128, chunk = 16 k (8 words), double-buffered, 48KB static smem.
#define BM 128
#define BN 128
#define SSTW 12      // padded words per smem row (16B-aligned: 48B)
#define CSZ (128 * SSTW)

__global__ __launch_bounds__(256, 2)
void gemm_hl() {
    __shared__ uint32_t S[2][4][CSZ];   // [buf][Ahi,Alo,Bhi,Blo]

    const int bm = blockIdx.y * BM;     // rows of R
    const int bn = blockIdx.x * BN;     // rows of L
    const int tid  = threadIdx.x;
    const int warp = tid >> 5;
    const int lane = tid & 31;
    const int wm = (warp & 3) * 32;     // warp tile 32(m) x 64(n)
    const int wn = (warp >> 2) * 64;

    // loader: per chunk per component 1024 words = 256 uint4; 1 uint4/thread
    const int l_row = tid >> 1;
    const int l_wb  = (tid & 1) * 4;

    const uint4* gAhi = (const uint4*)g_Rhi;   // A = R
    const uint4* gAlo = (const uint4*)g_Rlo;
    const uint4* gBhi = (const uint4*)g_Lhi;   // B = L
    const uint4* gBlo = (const uint4*)g_Llo;

    uint4 pa_h, pa_l, pb_h, pb_l;
    auto load_regs = [&](int c) {
        size_t ia = ((size_t)(bm + l_row) * WPR + c * 8 + l_wb) >> 2;
        size_t ib = ((size_t)(bn + l_row) * WPR + c * 8 + l_wb) >> 2;
        pa_h = gAhi[ia]; pa_l = gAlo[ia];
        pb_h = gBhi[ib]; pb_l = gBlo[ib];
    };
    auto store_smem = [&](int buf) {
        int off = l_row * SSTW + l_wb;
        *(uint4*)&S[buf][0][off] = pa_h;
        *(uint4*)&S[buf][1][off] = pa_l;
        *(uint4*)&S[buf][2][off] = pb_h;
        *(uint4*)&S[buf][3][off] = pb_l;
    };

    float acc[2][8][4];
#pragma unroll
    for (int im = 0; im < 2; im++)
#pragma unroll
        for (int in = 0; in < 8; in++)
#pragma unroll
            for (int q = 0; q < 4; q++) acc[im][in][q] = 0.0f;

    load_regs(0);
    store_smem(0);
    __syncthreads();

    const int NCHUNK = DD / 16;   // 32
    const int mrow = lane >> 2;
    const int kw   = lane & 3;

    for (int c = 0; c < NCHUNK; c++) {
        if (c + 1 < NCHUNK) load_regs(c + 1);

        const uint32_t* Ahi = S[c & 1][0];
        const uint32_t* Alo = S[c & 1][1];
        const uint32_t* Bhi = S[c & 1][2];
        const uint32_t* Blo = S[c & 1][3];

        uint32_t afh[2][4], afl[2][4];
#pragma unroll
        for (int im = 0; im < 2; im++) {
            int m = wm + im * 16 + mrow;
            afh[im][0] = Ahi[(m    ) * SSTW + kw    ];
            afh[im][1] = Ahi[(m + 8) * SSTW + kw    ];
            afh[im][2] = Ahi[(m    ) * SSTW + kw + 4];
            afh[im][3] = Ahi[(m + 8) * SSTW + kw + 4];
            afl[im][0] = Alo[(m    ) * SSTW + kw    ];
            afl[im][1] = Alo[(m + 8) * SSTW + kw    ];
            afl[im][2] = Alo[(m    ) * SSTW + kw + 4];
            afl[im][3] = Alo[(m + 8) * SSTW + kw + 4];
        }
#pragma unroll
        for (int in = 0; in < 8; in++) {
            int n = wn + in * 8 + mrow;
            uint32_t bh0 = Bhi[n * SSTW + kw    ];
            uint32_t bh1 = Bhi[n * SSTW + kw + 4];
            uint32_t bl0 = Blo[n * SSTW + kw    ];
            uint32_t bl1 = Blo[n * SSTW + kw + 4];
#pragma unroll
            for (int im = 0; im < 2; im++) {
                mma_f16(acc[im][in], afh[im], bh0, bh1);  // hi*hi
                mma_f16(acc[im][in], afh[im], bl0, bl1);  // hi*lo
                mma_f16(acc[im][in], afl[im], bh0, bh1);  // lo*hi
            }
        }

        if (c + 1 < NCHUNK) store_smem((c + 1) & 1);
        __syncthreads();
    }

    // epilogue (same layout as m16n8k8: rows m/m+8, cols 2*(lane&3))
#pragma unroll
    for (int im = 0; im < 2; im++) {
#pragma unroll
        for (int in = 0; in < 8; in++) {
            int m = bm + wm + im * 16 + (lane >> 2);
            int n = bn + wn + in * 8 + 2 * (lane & 3);
            *(float2*)&g_simT[(size_t)m * NN + n]       = make_float2(acc[im][in][0], acc[im][in][1]);
            *(float2*)&g_simT[(size_t)(m + 8) * NN + n] = make_float2(acc[im][in][2], acc[im][in][3]);
        }
    }
}

// ---------------- top-10 insertion (t ascending; t[0] = current min) ----------
__device__ __forceinline__ void insert10(float* t, float v) {
    if (v > t[0]) {
        t[0] = v;
#pragma unroll
        for (int i = 0; i < 9; i++) {
            if (t[i] > t[i + 1]) { float tmp = t[i]; t[i] = t[i + 1]; t[i + 1] = tmp; }
        }
    }
}

#define SENT (-1e30f)

// ---------------- RL: per-row top-10 mean of simT ----------------------------
__global__ __launch_bounds__(256)
void row_topk_mean() {
    __shared__ float s[256 * 10];
    const int row = blockIdx.x;
    const int tid = threadIdx.x;
    const float4* p = (const float4*)(g_simT + (size_t)row * NN);

    float t[10];
#pragma unroll
    for (int i = 0; i < 10; i++) t[i] = SENT;

    for (int j = tid; j < NN / 4; j += 256) {
        float4 v = p[j];
        insert10(t, v.x); insert10(t, v.y); insert10(t, v.z); insert10(t, v.w);
    }
#pragma unroll
    for (int i = 0; i < 10; i++) s[tid * 10 + i] = t[i];
    __syncthreads();

    if (tid < 32) {
#pragma unroll
        for (int i = 0; i < 10; i++) t[i] = s[tid * 10 + i];
        for (int src = tid + 32; src < 256; src += 32)
#pragma unroll
            for (int i = 0; i < 10; i++) insert10(t, s[src * 10 + i]);
#pragma unroll
        for (int i = 0; i < 10; i++) s[tid * 10 + i] = t[i];
    }
    __syncthreads();

    if (tid == 0) {
#pragma unroll
        for (int i = 0; i < 10; i++) t[i] = s[i];
        for (int src = 1; src < 32; src++)
#pragma unroll
            for (int i = 0; i < 10; i++) insert10(t, s[src * 10 + i]);
        float sum = 0.0f;
#pragma unroll
        for (int i = 0; i < 10; i++) sum += t[i];
        g_RL[row] = sum * 0.1f;
    }
}

// ---------------- LR: per-column top-10 mean of simT -------------------------
__global__ __launch_bounds__(256)
void col_topk_mean() {
    __shared__ float s[256 * 10];
    const int tid = threadIdx.x;
    const int col = blockIdx.x * 64 + (tid & 63);
    const int q   = tid >> 6;   // 0..3

    float t[10];
#pragma unroll
    for (int i = 0; i < 10; i++) t[i] = SENT;

    const float* base = g_simT + (size_t)q * 4096 * NN + col;
    for (int r = 0; r < 4096; r++) {
        insert10(t, base[(size_t)r * NN]);
    }
#pragma unroll
    for (int i = 0; i < 10; i++) s[tid * 10 + i] = t[i];
    __syncthreads();

    if (q == 0) {
#pragma unroll
        for (int p = 1; p < 4; p++)
#pragma unroll
            for (int i = 0; i < 10; i++) insert10(t, s[(tid + p * 64) * 10 + i]);
        float sum = 0.0f;
#pragma unroll
        for (int i = 0; i < 10; i++) sum += t[i];
        g_LR[col] = sum * 0.1f;
    }
}

// ---------------- P = LR + RL ------------------------------------------------
__global__ void compute_p() {
    int i = blockIdx.x * 256 + threadIdx.x;
    g_P[i] = g_LR[i] + g_RL[i];
}

// ---------------- rank + top1 over csls rows ---------------------------------
// csls[i][j] = 2*simT[i][j] - P[j]; rank = #gt + #eq(j<i); ranks as FLOAT.
__global__ __launch_bounds__(256)
void rank_top1(float* __restrict__ ranks, float* __restrict__ top1) {
    __shared__ int   s_gt[256];
    __shared__ int   s_eq[256];
    __shared__ float s_mx[256];

    const int i   = blockIdx.x;
    const int tid = threadIdx.x;
    const float* prow = g_simT + (size_t)i * NN;
    const float d = 2.0f * prow[i] - g_P[i];

    int cnt_gt = 0, cnt_eq = 0;
    float mx = SENT;

    const float4* pv = (const float4*)prow;
    const float4* qv = (const float4*)g_P;
    for (int j4 = tid; j4 < NN / 4; j4 += 256) {
        float4 v = pv[j4];
        float4 q = qv[j4];
        int j = j4 * 4;
        float c0 = 2.0f * v.x - q.x;
        float c1 = 2.0f * v.y - q.y;
        float c2 = 2.0f * v.z - q.z;
        float c3 = 2.0f * v.w - q.w;
        cnt_gt += (c0 > d) + (c1 > d) + (c2 > d) + (c3 > d);
        if (c0 == d && (j + 0) < i) cnt_eq++;
        if (c1 == d && (j + 1) < i) cnt_eq++;
        if (c2 == d && (j + 2) < i) cnt_eq++;
        if (c3 == d && (j + 3) < i) cnt_eq++;
        mx = fmaxf(mx, fmaxf(fmaxf(c0, c1), fmaxf(c2, c3)));
    }

    s_gt[tid] = cnt_gt; s_eq[tid] = cnt_eq; s_mx[tid] = mx;
    __syncthreads();
    for (int str = 128; str > 0; str >>= 1) {
        if (tid < str) {
            s_gt[tid] += s_gt[tid + str];
            s_eq[tid] += s_eq[tid + str];
            s_mx[tid] = fmaxf(s_mx[tid], s_mx[tid + str]);
        }
        __syncthreads();
    }
    if (tid == 0) {
        ranks[i] = (float)(s_gt[0] + s_eq[0]);
        top1[i]  = s_mx[0];
    }
}

// ---------------- launch ------------------------------------------------------
extern "C" void kernel_launch(void* const* d_in, const int* in_sizes, int n_in,
                              void* d_out, int out_size) {
    const float* L = (const float*)d_in[0];
    const float* R = (const float*)d_in[1];

    dim3 cgrid(NN * WPR / 256, 2);
    cvt_hl<<<cgrid, 256>>>(L, R);

    dim3 grid(NN / BN, NN / BM);
    gemm_hl<<<grid, 256>>>();

    row_topk_mean<<<NN, 256>>>();        // RL over simT rows
    col_topk_mean<<<NN / 64, 256>>>();   // LR over simT cols
    compute_p<<<NN / 256, 256>>>();

    float* ranks = (float*)d_out;
    float* top1  = (float*)d_out + NN;
    rank_top1<<<NN, 256>>>(ranks, top1);
}

// round 8
// speedup vs baseline: 1.8355x; 1.0758x over previous
#include <cuda_runtime.h>
#include <cuda_fp16.h>
#include <cstdint>
#include <cstddef>

#define NN 16384
#define DD 512
#define WPR 256   // half2 words per row (DD/2)

// ---------------- scratch (device globals; sanctioned) ------------------------
__device__ float    g_simT[(size_t)NN * NN]; // simT[i][j] = <R_i, L_j>
__device__ uint32_t g_Lhi[(size_t)NN * WPR];
__device__ uint32_t g_Llo[(size_t)NN * WPR];
__device__ uint32_t g_Rhi[(size_t)NN * WPR];
__device__ uint32_t g_Rlo[(size_t)NN * WPR];
__device__ float    g_LR[NN];
__device__ float    g_RL[NN];
__device__ float    g_P [NN];

// ---------------- precompute: fp16 hi/lo split, packed half2 ------------------
__global__ __launch_bounds__(256)
void cvt_hl(const float* __restrict__ L, const float* __restrict__ R) {
    const size_t w = (size_t)blockIdx.x * 256 + threadIdx.x;   // word index
    const float2* src = (blockIdx.y == 0) ? (const float2*)L : (const float2*)R;
    uint32_t* dhi = (blockIdx.y == 0) ? g_Lhi : g_Rhi;
    uint32_t* dlo = (blockIdx.y == 0) ? g_Llo : g_Rlo;

    float2 v = src[w];
    __half hx = __float2half_rn(v.x);
    __half hy = __float2half_rn(v.y);
    float lx = v.x - __half2float(hx);
    float ly = v.y - __half2float(hy);
    __half2 hhi = __halves2half2(hx, hy);
    __half2 hlo = __floats2half2_rn(lx, ly);
    dhi[w] = *(uint32_t*)&hhi;
    dlo[w] = *(uint32_t*)&hlo;
}

// ---------------- fp16 MMA + ldmatrix ----------------------------------------
__device__ __forceinline__ void mma_f16(float* c, const uint32_t* a, uint32_t b0, uint32_t b1) {
    asm volatile(
        "mma.sync.aligned.m16n8k16.row.col.f32.f16.f16.f32 "
        "{%0,%1,%2,%3}, {%4,%5,%6,%7}, {%8,%9}, {%0,%1,%2,%3};"
        : "+f"(c[0]), "+f"(c[1]), "+f"(c[2]), "+f"(c[3])
        : "r"(a[0]), "r"(a[1]), "r"(a[2]), "r"(a[3]), "r"(b0), "r"(b1));
}

__device__ __forceinline__ void ldsm4(uint32_t* r, uint32_t addr) {
    asm volatile("ldmatrix.sync.aligned.m8n8.x4.shared.b16 {%0,%1,%2,%3}, [%4];"
                 : "=r"(r[0]), "=r"(r[1]), "=r"(r[2]), "=r"(r[3]) : "r"(addr));
}

// ---------------- GEMM: simT = R . L^T  (3-term fp16 split) -------------------
// BM=BN=128, chunk = 16 k (8 words), double-buffered, 48KB static smem.
#define BM 128
#define BN 128
#define SSTW 12      // padded words per smem row (48B: conflict-free for ldmatrix)
#define CSZ (128 * SSTW)

__global__ __launch_bounds__(256, 2)
void gemm_hl() {
    __shared__ uint32_t S[2][4][CSZ];   // [buf][Ahi,Alo,Bhi,Blo]

    const int bm = blockIdx.y * BM;     // rows of R
    const int bn = blockIdx.x * BN;     // rows of L
    const int tid  = threadIdx.x;
    const int warp = tid >> 5;
    const int lane = tid & 31;
    const int wm = (warp & 3) * 32;     // warp tile 32(m) x 64(n)
    const int wn = (warp >> 2) * 64;

    // loader: per chunk per component 1024 words = 256 uint4; 1 uint4/thread
    const int l_row = tid >> 1;
    const int l_wb  = (tid & 1) * 4;

    const uint4* gAhi = (const uint4*)g_Rhi;   // A = R
    const uint4* gAlo = (const uint4*)g_Rlo;
    const uint4* gBhi = (const uint4*)g_Lhi;   // B = L
    const uint4* gBlo = (const uint4*)g_Llo;

    uint4 pa_h, pa_l, pb_h, pb_l;
    auto load_regs = [&](int c) {
        size_t ia = ((size_t)(bm + l_row) * WPR + c * 8 + l_wb) >> 2;
        size_t ib = ((size_t)(bn + l_row) * WPR + c * 8 + l_wb) >> 2;
        pa_h = gAhi[ia]; pa_l = gAlo[ia];
        pb_h = gBhi[ib]; pb_l = gBlo[ib];
    };
    auto store_smem = [&](int buf) {
        int off = l_row * SSTW + l_wb;
        *(uint4*)&S[buf][0][off] = pa_h;
        *(uint4*)&S[buf][1][off] = pa_l;
        *(uint4*)&S[buf][2][off] = pb_h;
        *(uint4*)&S[buf][3][off] = pb_l;
    };

    // ldmatrix lane->address words (within a component)
    const uint32_t sb = (uint32_t)__cvta_generic_to_shared(&S[0][0][0]);
    const uint32_t aW = (uint32_t)((wm + (lane & 15)) * SSTW + ((lane >> 4) << 2));
    const uint32_t bW = (uint32_t)((wn + (lane & 7) + ((lane >> 4) << 3)) * SSTW +
                                   (((lane >> 3) & 1) << 2));

    float acc[2][8][4];
#pragma unroll
    for (int im = 0; im < 2; im++)
#pragma unroll
        for (int in = 0; in < 8; in++)
#pragma unroll
            for (int q = 0; q < 4; q++) acc[im][in][q] = 0.0f;

    load_regs(0);
    store_smem(0);
    __syncthreads();

    const int NCHUNK = DD / 16;   // 32
    for (int c = 0; c < NCHUNK; c++) {
        if (c + 1 < NCHUNK) load_regs(c + 1);

        const uint32_t bufoff = (uint32_t)((c & 1) * 4 * CSZ);
        const uint32_t aHiA = sb + (bufoff + 0 * CSZ + aW) * 4;
        const uint32_t aLoA = sb + (bufoff + 1 * CSZ + aW) * 4;
        const uint32_t bHiA = sb + (bufoff + 2 * CSZ + bW) * 4;
        const uint32_t bLoA = sb + (bufoff + 3 * CSZ + bW) * 4;

        uint32_t afh[2][4], afl[2][4];
#pragma unroll
        for (int im = 0; im < 2; im++) {
            ldsm4(afh[im], aHiA + im * 16 * SSTW * 4);
            ldsm4(afl[im], aLoA + im * 16 * SSTW * 4);
        }
#pragma unroll
        for (int inp = 0; inp < 4; inp++) {
            uint32_t bh[4], bl[4];
            ldsm4(bh, bHiA + inp * 16 * SSTW * 4);
            ldsm4(bl, bLoA + inp * 16 * SSTW * 4);
#pragma unroll
            for (int s = 0; s < 2; s++) {
                const int in = inp * 2 + s;
#pragma unroll
                for (int im = 0; im < 2; im++) {
                    mma_f16(acc[im][in], afh[im], bh[2 * s], bh[2 * s + 1]);  // hi*hi
                    mma_f16(acc[im][in], afh[im], bl[2 * s], bl[2 * s + 1]);  // hi*lo
                    mma_f16(acc[im][in], afl[im], bh[2 * s], bh[2 * s + 1]);  // lo*hi
                }
            }
        }

        if (c + 1 < NCHUNK) store_smem((c + 1) & 1);
        __syncthreads();
    }

    // epilogue
#pragma unroll
    for (int im = 0; im < 2; im++) {
#pragma unroll
        for (int in = 0; in < 8; in++) {
            int m = bm + wm + im * 16 + (lane >> 2);
            int n = bn + wn + in * 8 + 2 * (lane & 3);
            *(float2*)&g_simT[(size_t)m * NN + n]       = make_float2(acc[im][in][0], acc[im][in][1]);
            *(float2*)&g_simT[(size_t)(m + 8) * NN + n] = make_float2(acc[im][in][2], acc[im][in][3]);
        }
    }
}

// ---------------- top-10 insertion (t ascending; t[0] = current min) ----------
__device__ __forceinline__ void insert10(float* t, float v) {
    if (v > t[0]) {
        t[0] = v;
#pragma unroll
        for (int i = 0; i < 9; i++) {
            if (t[i] > t[i + 1]) { float tmp = t[i]; t[i] = t[i + 1]; t[i + 1] = tmp; }
        }
    }
}

#define SENT (-1e30f)

// ---------------- RL: per-row top-10 mean of simT ----------------------------
__global__ __launch_bounds__(256)
void row_topk_mean() {
    __shared__ float s[256 * 10];
    const int row = blockIdx.x;
    const int tid = threadIdx.x;
    const float4* p = (const float4*)(g_simT + (size_t)row * NN);

    float t[10];
#pragma unroll
    for (int i = 0; i < 10; i++) t[i] = SENT;

    for (int j = tid; j < NN / 4; j += 256) {
        float4 v = p[j];
        insert10(t, v.x); insert10(t, v.y); insert10(t, v.z); insert10(t, v.w);
    }
#pragma unroll
    for (int i = 0; i < 10; i++) s[tid * 10 + i] = t[i];
    __syncthreads();

    if (tid < 32) {
#pragma unroll
        for (int i = 0; i < 10; i++) t[i] = s[tid * 10 + i];
        for (int src = tid + 32; src < 256; src += 32)
#pragma unroll
            for (int i = 0; i < 10; i++) insert10(t, s[src * 10 + i]);
#pragma unroll
        for (int i = 0; i < 10; i++) s[tid * 10 + i] = t[i];
    }
    __syncthreads();

    if (tid == 0) {
#pragma unroll
        for (int i = 0; i < 10; i++) t[i] = s[i];
        for (int src = 1; src < 32; src++)
#pragma unroll
            for (int i = 0; i < 10; i++) insert10(t, s[src * 10 + i]);
        float sum = 0.0f;
#pragma unroll
        for (int i = 0; i < 10; i++) sum += t[i];
        g_RL[row] = sum * 0.1f;
    }
}

// ---------------- LR: per-column top-10 mean of simT (coalesced) --------------
// 128 blocks x 512 threads: thread handles one column over a quarter of rows.
// Consecutive threads -> consecutive columns (fully coalesced row reads).
__global__ __launch_bounds__(512)
void col_topk_mean() {
    __shared__ float s[512 * 10];
    const int tid = threadIdx.x;
    const int col = blockIdx.x * 128 + (tid & 127);
    const int q   = tid >> 7;   // 0..3 row quarter

    float t[10];
#pragma unroll
    for (int i = 0; i < 10; i++) t[i] = SENT;

    const float* base = g_simT + (size_t)q * 4096 * NN + col;
#pragma unroll 1
    for (int r = 0; r < 4096; r += 4) {
        float v0 = base[(size_t)(r + 0) * NN];
        float v1 = base[(size_t)(r + 1) * NN];
        float v2 = base[(size_t)(r + 2) * NN];
        float v3 = base[(size_t)(r + 3) * NN];
        insert10(t, v0); insert10(t, v1); insert10(t, v2); insert10(t, v3);
    }
#pragma unroll
    for (int i = 0; i < 10; i++) s[tid * 10 + i] = t[i];
    __syncthreads();

    if (q == 0) {
#pragma unroll
        for (int p = 1; p < 4; p++)
#pragma unroll
            for (int i = 0; i < 10; i++) insert10(t, s[(tid + p * 128) * 10 + i]);
        float sum = 0.0f;
#pragma unroll
        for (int i = 0; i < 10; i++) sum += t[i];
        g_LR[col] = sum * 0.1f;
    }
}

// ---------------- P = LR + RL ------------------------------------------------
__global__ void compute_p() {
    int i = blockIdx.x * 256 + threadIdx.x;
    g_P[i] = g_LR[i] + g_RL[i];
}

// ---------------- rank + top1 over csls rows ---------------------------------
// csls[i][j] = 2*simT[i][j] - P[j]; rank = #gt + #eq(j<i); ranks as FLOAT.
__global__ __launch_bounds__(256)
void rank_top1(float* __restrict__ ranks, float* __restrict__ top1) {
    __shared__ int   s_gt[256];
    __shared__ int   s_eq[256];
    __shared__ float s_mx[256];

    const int i   = blockIdx.x;
    const int tid = threadIdx.x;
    const float* prow = g_simT + (size_t)i * NN;
    const float d = 2.0f * prow[i] - g_P[i];

    int cnt_gt = 0, cnt_eq = 0;
    float mx = SENT;

    const float4* pv = (const float4*)prow;
    const float4* qv = (const float4*)g_P;
    for (int j4 = tid; j4 < NN / 4; j4 += 256) {
        float4 v = pv[j4];
        float4 q = qv[j4];
        int j = j4 * 4;
        float c0 = 2.0f * v.x - q.x;
        float c1 = 2.0f * v.y - q.y;
        float c2 = 2.0f * v.z - q.z;
        float c3 = 2.0f * v.w - q.w;
        cnt_gt += (c0 > d) + (c1 > d) + (c2 > d) + (c3 > d);
        if (c0 == d && (j + 0) < i) cnt_eq++;
        if (c1 == d && (j + 1) < i) cnt_eq++;
        if (c2 == d && (j + 2) < i) cnt_eq++;
        if (c3 == d && (j + 3) < i) cnt_eq++;
        mx = fmaxf(mx, fmaxf(fmaxf(c0, c1), fmaxf(c2, c3)));
    }

    s_gt[tid] = cnt_gt; s_eq[tid] = cnt_eq; s_mx[tid] = mx;
    __syncthreads();
    for (int str = 128; str > 0; str >>= 1) {
        if (tid < str) {
            s_gt[tid] += s_gt[tid + str];
            s_eq[tid] += s_eq[tid + str];
            s_mx[tid] = fmaxf(s_mx[tid], s_mx[tid + str]);
        }
        __syncthreads();
    }
    if (tid == 0) {
        ranks[i] = (float)(s_gt[0] + s_eq[0]);
        top1[i]  = s_mx[0];
    }
}

// ---------------- launch ------------------------------------------------------
extern "C" void kernel_launch(void* const* d_in, const int* in_sizes, int n_in,
                              void* d_out, int out_size) {
    const float* L = (const float*)d_in[0];
    const float* R = (const float*)d_in[1];

    dim3 cgrid(NN * WPR / 256, 2);
    cvt_hl<<<cgrid, 256>>>(L, R);

    dim3 grid(NN / BN, NN / BM);
    gemm_hl<<<grid, 256>>>();

    row_topk_mean<<<NN, 256>>>();        // RL over simT rows
    col_topk_mean<<<NN / 128, 512>>>();  // LR over simT cols (coalesced)
    compute_p<<<NN / 256, 256>>>();

    float* ranks = (float*)d_out;
    float* top1  = (float*)d_out + NN;
    rank_top1<<<NN, 256>>>(ranks, top1);
}

// round 9
// speedup vs baseline: 2.6830x; 1.4617x over previous
#include <cuda_runtime.h>
#include <cuda_fp16.h>
#include <cstdint>
#include <cstddef>

#define NN 16384
#define DD 512
#define WPR 256   // half2 words per row (DD/2)
#define NSEG 16   // column-topk row segments

// ---------------- scratch (device globals; sanctioned) ------------------------
__device__ float    g_simT[(size_t)NN * NN]; // simT[i][j] = <R_i, L_j>
__device__ uint32_t g_Lhi[(size_t)NN * WPR];
__device__ uint32_t g_Llo[(size_t)NN * WPR];
__device__ uint32_t g_Rhi[(size_t)NN * WPR];
__device__ float    g_part[NSEG][NN][10];    // per-segment column top-10
__device__ float    g_LR[NN];
__device__ float    g_RL[NN];
__device__ float    g_P [NN];

// ---------------- precompute: fp16 hi/lo split, packed half2 ------------------
// A-side (R) needs only hi; B-side (L) needs hi+lo (2-term split keeps Ahi*Blo).
__global__ __launch_bounds__(256)
void cvt_hl(const float* __restrict__ L, const float* __restrict__ R) {
    const size_t w = (size_t)blockIdx.x * 256 + threadIdx.x;   // word index
    if (blockIdx.y == 0) {
        float2 v = ((const float2*)L)[w];
        __half hx = __float2half_rn(v.x);
        __half hy = __float2half_rn(v.y);
        float lx = v.x - __half2float(hx);
        float ly = v.y - __half2float(hy);
        __half2 hhi = __halves2half2(hx, hy);
        __half2 hlo = __floats2half2_rn(lx, ly);
        g_Lhi[w] = *(uint32_t*)&hhi;
        g_Llo[w] = *(uint32_t*)&hlo;
    } else {
        float2 v = ((const float2*)R)[w];
        __half2 hhi = __floats2half2_rn(v.x, v.y);
        g_Rhi[w] = *(uint32_t*)&hhi;
    }
}

// ---------------- fp16 MMA + ldmatrix ----------------------------------------
__device__ __forceinline__ void mma_f16(float* c, const uint32_t* a, uint32_t b0, uint32_t b1) {
    asm volatile(
        "mma.sync.aligned.m16n8k16.row.col.f32.f16.f16.f32 "
        "{%0,%1,%2,%3}, {%4,%5,%6,%7}, {%8,%9}, {%0,%1,%2,%3};"
        : "+f"(c[0]), "+f"(c[1]), "+f"(c[2]), "+f"(c[3])
        : "r"(a[0]), "r"(a[1]), "r"(a[2]), "r"(a[3]), "r"(b0), "r"(b1));
}

__device__ __forceinline__ void ldsm4(uint32_t* r, uint32_t addr) {
    asm volatile("ldmatrix.sync.aligned.m8n8.x4.shared.b16 {%0,%1,%2,%3}, [%4];"
                 : "=r"(r[0]), "=r"(r[1]), "=r"(r[2]), "=r"(r[3]) : "r"(addr));
}

// ---------------- GEMM: simT = R . L^T  (2-term fp16 split) -------------------
// C = Ahi*Bhi + Ahi*Blo.  BM=BN=128, chunk=16 k, double-buffered, 36KB smem.
#define BM 128
#define BN 128
#define SSTW 12      // padded words per smem row (48B: conflict-free for ldmatrix)
#define CSZ (128 * SSTW)

__global__ __launch_bounds__(256, 2)
void gemm_hl() {
    __shared__ uint32_t S[2][3][CSZ];   // [buf][Ahi,Bhi,Blo]

    const int bm = blockIdx.y * BM;     // rows of R
    const int bn = blockIdx.x * BN;     // rows of L
    const int tid  = threadIdx.x;
    const int warp = tid >> 5;
    const int lane = tid & 31;
    const int wm = (warp & 3) * 32;     // warp tile 32(m) x 64(n)
    const int wn = (warp >> 2) * 64;

    const int l_row = tid >> 1;
    const int l_wb  = (tid & 1) * 4;

    const uint4* gAhi = (const uint4*)g_Rhi;   // A = R
    const uint4* gBhi = (const uint4*)g_Lhi;   // B = L
    const uint4* gBlo = (const uint4*)g_Llo;

    uint4 pa_h, pb_h, pb_l;
    auto load_regs = [&](int c) {
        size_t ia = ((size_t)(bm + l_row) * WPR + c * 8 + l_wb) >> 2;
        size_t ib = ((size_t)(bn + l_row) * WPR + c * 8 + l_wb) >> 2;
        pa_h = gAhi[ia];
        pb_h = gBhi[ib]; pb_l = gBlo[ib];
    };
    auto store_smem = [&](int buf) {
        int off = l_row * SSTW + l_wb;
        *(uint4*)&S[buf][0][off] = pa_h;
        *(uint4*)&S[buf][1][off] = pb_h;
        *(uint4*)&S[buf][2][off] = pb_l;
    };

    const uint32_t sb = (uint32_t)__cvta_generic_to_shared(&S[0][0][0]);
    const uint32_t aW = (uint32_t)((wm + (lane & 15)) * SSTW + ((lane >> 4) << 2));
    const uint32_t bW = (uint32_t)((wn + (lane & 7) + ((lane >> 4) << 3)) * SSTW +
                                   (((lane >> 3) & 1) << 2));

    float acc[2][8][4];
#pragma unroll
    for (int im = 0; im < 2; im++)
#pragma unroll
        for (int in = 0; in < 8; in++)
#pragma unroll
            for (int q = 0; q < 4; q++) acc[im][in][q] = 0.0f;

    load_regs(0);
    store_smem(0);
    __syncthreads();

    const int NCHUNK = DD / 16;   // 32
    for (int c = 0; c < NCHUNK; c++) {
        if (c + 1 < NCHUNK) load_regs(c + 1);

        const uint32_t bufoff = (uint32_t)((c & 1) * 3 * CSZ);
        const uint32_t aHiA = sb + (bufoff + 0 * CSZ + aW) * 4;
        const uint32_t bHiA = sb + (bufoff + 1 * CSZ + bW) * 4;
        const uint32_t bLoA = sb + (bufoff + 2 * CSZ + bW) * 4;

        uint32_t afh[2][4];
#pragma unroll
        for (int im = 0; im < 2; im++)
            ldsm4(afh[im], aHiA + im * 16 * SSTW * 4);

#pragma unroll
        for (int inp = 0; inp < 4; inp++) {
            uint32_t bh[4], bl[4];
            ldsm4(bh, bHiA + inp * 16 * SSTW * 4);
            ldsm4(bl, bLoA + inp * 16 * SSTW * 4);
#pragma unroll
            for (int s = 0; s < 2; s++) {
                const int in = inp * 2 + s;
#pragma unroll
                for (int im = 0; im < 2; im++) {
                    mma_f16(acc[im][in], afh[im], bh[2 * s], bh[2 * s + 1]);  // hi*hi
                    mma_f16(acc[im][in], afh[im], bl[2 * s], bl[2 * s + 1]);  // hi*lo
                }
            }
        }

        if (c + 1 < NCHUNK) store_smem((c + 1) & 1);
        __syncthreads();
    }

    // epilogue
#pragma unroll
    for (int im = 0; im < 2; im++) {
#pragma unroll
        for (int in = 0; in < 8; in++) {
            int m = bm + wm + im * 16 + (lane >> 2);
            int n = bn + wn + in * 8 + 2 * (lane & 3);
            *(float2*)&g_simT[(size_t)m * NN + n]       = make_float2(acc[im][in][0], acc[im][in][1]);
            *(float2*)&g_simT[(size_t)(m + 8) * NN + n] = make_float2(acc[im][in][2], acc[im][in][3]);
        }
    }
}

// ---------------- top-10 insertion (t ascending; t[0] = current min) ----------
__device__ __forceinline__ void insert10(float* t, float v) {
    if (v > t[0]) {
        t[0] = v;
#pragma unroll
        for (int i = 0; i < 9; i++) {
            if (t[i] > t[i + 1]) { float tmp = t[i]; t[i] = t[i + 1]; t[i + 1] = tmp; }
        }
    }
}

#define SENT (-1e30f)

// ---------------- RL: per-row top-10 mean of simT ----------------------------
__global__ __launch_bounds__(256)
void row_topk_mean() {
    __shared__ float s[256 * 10];
    const int row = blockIdx.x;
    const int tid = threadIdx.x;
    const float4* p = (const float4*)(g_simT + (size_t)row * NN);

    float t[10];
#pragma unroll
    for (int i = 0; i < 10; i++) t[i] = SENT;

    for (int j = tid; j < NN / 4; j += 256) {
        float4 v = p[j];
        insert10(t, v.x); insert10(t, v.y); insert10(t, v.z); insert10(t, v.w);
    }
#pragma unroll
    for (int i = 0; i < 10; i++) s[tid * 10 + i] = t[i];
    __syncthreads();

    if (tid < 32) {
#pragma unroll
        for (int i = 0; i < 10; i++) t[i] = s[tid * 10 + i];
        for (int src = tid + 32; src < 256; src += 32)
#pragma unroll
            for (int i = 0; i < 10; i++) insert10(t, s[src * 10 + i]);
#pragma unroll
        for (int i = 0; i < 10; i++) s[tid * 10 + i] = t[i];
    }
    __syncthreads();

    if (tid == 0) {
#pragma unroll
        for (int i = 0; i < 10; i++) t[i] = s[i];
        for (int src = 1; src < 32; src++)
#pragma unroll
            for (int i = 0; i < 10; i++) insert10(t, s[src * 10 + i]);
        float sum = 0.0f;
#pragma unroll
        for (int i = 0; i < 10; i++) sum += t[i];
        g_RL[row] = sum * 0.1f;
    }
}

// ---------------- LR stage 1: per-segment column top-10 -----------------------
// grid (64, NSEG), 256 threads: one column per thread, 1024 rows per segment,
// unroll-8 for MLP. Fully coalesced (consecutive threads -> consecutive cols).
__global__ __launch_bounds__(256)
void col_topk_part() {
    const int col = blockIdx.x * 256 + threadIdx.x;
    const int seg = blockIdx.y;

    float t[10];
#pragma unroll
    for (int i = 0; i < 10; i++) t[i] = SENT;

    const float* base = g_simT + (size_t)seg * (NN / NSEG) * NN + col;
#pragma unroll 1
    for (int r = 0; r < NN / NSEG; r += 8) {
        float v0 = base[(size_t)(r + 0) * NN];
        float v1 = base[(size_t)(r + 1) * NN];
        float v2 = base[(size_t)(r + 2) * NN];
        float v3 = base[(size_t)(r + 3) * NN];
        float v4 = base[(size_t)(r + 4) * NN];
        float v5 = base[(size_t)(r + 5) * NN];
        float v6 = base[(size_t)(r + 6) * NN];
        float v7 = base[(size_t)(r + 7) * NN];
        insert10(t, v0); insert10(t, v1); insert10(t, v2); insert10(t, v3);
        insert10(t, v4); insert10(t, v5); insert10(t, v6); insert10(t, v7);
    }
#pragma unroll
    for (int i = 0; i < 10; i++) g_part[seg][col][i] = t[i];
}

// ---------------- LR stage 2: merge segments ---------------------------------
__global__ __launch_bounds__(256)
void col_topk_reduce() {
    const int col = blockIdx.x * 256 + threadIdx.x;
    float t[10];
#pragma unroll
    for (int i = 0; i < 10; i++) t[i] = g_part[0][col][i];
#pragma unroll
    for (int seg = 1; seg < NSEG; seg++)
#pragma unroll
        for (int i = 0; i < 10; i++) insert10(t, g_part[seg][col][i]);
    float sum = 0.0f;
#pragma unroll
    for (int i = 0; i < 10; i++) sum += t[i];
    g_LR[col] = sum * 0.1f;
}

// ---------------- P = LR + RL ------------------------------------------------
__global__ void compute_p() {
    int i = blockIdx.x * 256 + threadIdx.x;
    g_P[i] = g_LR[i] + g_RL[i];
}

// ---------------- rank + top1 over csls rows ---------------------------------
// csls[i][j] = 2*simT[i][j] - P[j]; rank = #gt + #eq(j<i); ranks as FLOAT.
__global__ __launch_bounds__(256)
void rank_top1(float* __restrict__ ranks, float* __restrict__ top1) {
    __shared__ int   s_gt[256];
    __shared__ int   s_eq[256];
    __shared__ float s_mx[256];

    const int i   = blockIdx.x;
    const int tid = threadIdx.x;
    const float* prow = g_simT + (size_t)i * NN;
    const float d = 2.0f * prow[i] - g_P[i];

    int cnt_gt = 0, cnt_eq = 0;
    float mx = SENT;

    const float4* pv = (const float4*)prow;
    const float4* qv = (const float4*)g_P;
    for (int j4 = tid; j4 < NN / 4; j4 += 256) {
        float4 v = pv[j4];
        float4 q = qv[j4];
        int j = j4 * 4;
        float c0 = 2.0f * v.x - q.x;
        float c1 = 2.0f * v.y - q.y;
        float c2 = 2.0f * v.z - q.z;
        float c3 = 2.0f * v.w - q.w;
        cnt_gt += (c0 > d) + (c1 > d) + (c2 > d) + (c3 > d);
        if (c0 == d && (j + 0) < i) cnt_eq++;
        if (c1 == d && (j + 1) < i) cnt_eq++;
        if (c2 == d && (j + 2) < i) cnt_eq++;
        if (c3 == d && (j + 3) < i) cnt_eq++;
        mx = fmaxf(mx, fmaxf(fmaxf(c0, c1), fmaxf(c2, c3)));
    }

    s_gt[tid] = cnt_gt; s_eq[tid] = cnt_eq; s_mx[tid] = mx;
    __syncthreads();
    for (int str = 128; str > 0; str >>= 1) {
        if (tid < str) {
            s_gt[tid] += s_gt[tid + str];
            s_eq[tid] += s_eq[tid + str];
            s_mx[tid] = fmaxf(s_mx[tid], s_mx[tid + str]);
        }
        __syncthreads();
    }
    if (tid == 0) {
        ranks[i] = (float)(s_gt[0] + s_eq[0]);
        top1[i]  = s_mx[0];
    }
}

// ---------------- launch ------------------------------------------------------
extern "C" void kernel_launch(void* const* d_in, const int* in_sizes, int n_in,
                              void* d_out, int out_size) {
    const float* L = (const float*)d_in[0];
    const float* R = (const float*)d_in[1];

    dim3 cgrid(NN * WPR / 256, 2);
    cvt_hl<<<cgrid, 256>>>(L, R);

    dim3 grid(NN / BN, NN / BM);
    gemm_hl<<<grid, 256>>>();

    row_topk_mean<<<NN, 256>>>();                 // RL over simT rows
    col_topk_part<<<dim3(NN / 256, NSEG), 256>>>();  // LR stage 1
    col_topk_reduce<<<NN / 256, 256>>>();            // LR stage 2
    compute_p<<<NN / 256, 256>>>();

    float* ranks = (float*)d_out;
    float* top1  = (float*)d_out + NN;
    rank_top1<<<NN, 256>>>(ranks, top1);
}